// round 6
// baseline (speedup 1.0000x reference)
#include <cuda_runtime.h>
#include <math.h>

// ---------------- problem constants ----------------
#define H_IMG 110
#define W_IMG 110
#define NPIX  (H_IMG * W_IMG)      // 12100
#define OHW   96
#define NOUT  (OHW * OHW)          // 9216
#define NBC   8                    // b*c = 2*4
#define NPLANE (NBC * 2)           // 16 (bc, t)
#define EPSF  1e-8f
#define SPEC_U 1.4142135623730951e-3f
#define TEMP_U 1.4142135623730951e-3f

// ---------------- scratch (static: no allocation allowed) ----------------
__device__ float4 g_q[NPLANE * NPIX];    // (spec, temp, G, val)
__device__ float  g_pfn[NPLANE * NPIX];  // pf if valid else NaN
__device__ float  g_thr;
__device__ float2 g_ps[2 * NPLANE][NOUT]; // per-(half, bc, t) partial (S0, S1)

#define PREP_BLOCKS  256
#define PREP_THREADS 256
__device__ float g_part[PREP_BLOCKS][3];
__device__ unsigned int g_ticket = 0;

__device__ __forceinline__ int wcount(int i) {   // #windows covering index i
    int lo = i - 14; if (lo < 0) lo = 0;
    int hi = i;      if (hi > 95) hi = 95;
    return hi - lo + 1;
}

__device__ __forceinline__ float warp_redf(float v) {
    #pragma unroll
    for (int o = 16; o > 0; o >>= 1) v += __shfl_down_sync(0xffffffffu, v, o);
    return v;
}

// ---------------- pass 1: per-pixel precompute + fused thr reduction --------
__global__ __launch_bounds__(PREP_THREADS)
void prep_kernel(const float* __restrict__ pcg,
                 const float* __restrict__ pfg,
                 const float* __restrict__ pdg)
{
    // Kahan-compensated fp32 accumulation (no FP64 in the hot path)
    float c = 0.f, s = 0.f, s2 = 0.f;
    float cc_ = 0.f, cs_ = 0.f, cs2_ = 0.f;
    const int total = NPLANE * NPIX;
    for (int idx = blockIdx.x * blockDim.x + threadIdx.x; idx < total;
         idx += gridDim.x * blockDim.x) {
        int p   = idx / NPIX;
        int pix = idx - p * NPIX;
        float vpc = pcg[idx];
        float vpf = pfg[idx];
        float vpd = pdg[(p >> 1) * NPIX + pix];

        float spec = fabsf(vpc - vpf);
        float temp = fabsf(vpc - vpd);
        float G    = logf(spec + 1.0f) * logf(temp + 1.0f);
        float val  = (vpd + vpf) - vpc;

        g_q[idx]   = make_float4(spec, temp, G, val);
        g_pfn[idx] = (vpf >= EPSF) ? vpf : __int_as_float(0x7fffffff); // NaN

        if (vpf >= EPSF) {
            int h = pix / W_IMG, w = pix - h * W_IMG;
            float mult = (float)(wcount(h) * wcount(w));
            // Kahan add of (mult, mult*vpf, mult*vpf*vpf)
            float t0 = mult;
            float y = t0 - cc_;  float tt = c + y;  cc_  = (tt - c) - y;  c  = tt;
            float t1 = mult * vpf;
            y = t1 - cs_;        tt = s + y;        cs_  = (tt - s) - y;  s  = tt;
            float t2 = t1 * vpf;
            y = t2 - cs2_;       tt = s2 + y;       cs2_ = (tt - s2) - y; s2 = tt;
        }
    }

    __shared__ float sm[8][3];
    __shared__ int isLast;
    const int tid = threadIdx.x, warp = tid >> 5, lane = tid & 31;
    c = warp_redf(c); s = warp_redf(s); s2 = warp_redf(s2);
    if (lane == 0) { sm[warp][0] = c; sm[warp][1] = s; sm[warp][2] = s2; }
    __syncthreads();
    if (tid == 0) {
        float C = 0, S = 0, S2 = 0;
        #pragma unroll
        for (int w = 0; w < 8; w++) { C += sm[w][0]; S += sm[w][1]; S2 += sm[w][2]; }
        g_part[blockIdx.x][0] = C; g_part[blockIdx.x][1] = S; g_part[blockIdx.x][2] = S2;
        __threadfence();
        unsigned t = atomicAdd(&g_ticket, 1u);
        isLast = (t == PREP_BLOCKS - 1);
    }
    __syncthreads();
    if (isLast) {
        __threadfence();
        float cc = 0, ss = 0, ss2 = 0;
        if (tid < PREP_BLOCKS) {          // 256 threads, 256 partials
            cc = g_part[tid][0]; ss = g_part[tid][1]; ss2 = g_part[tid][2];
        }
        cc = warp_redf(cc); ss = warp_redf(ss); ss2 = warp_redf(ss2);
        if (lane == 0) { sm[warp][0] = cc; sm[warp][1] = ss; sm[warp][2] = ss2; }
        __syncthreads();
        if (tid == 0) {
            float C = 0, S = 0, S2 = 0;
            #pragma unroll
            for (int w = 0; w < 8; w++) { C += sm[w][0]; S += sm[w][1]; S2 += sm[w][2]; }
            double m = (double)S / (double)C, m2 = (double)S2 / (double)C;
            g_thr = (float)(2.0 * sqrt(m2 - m * m) / 5.0);
            g_ticket = 0;     // reset for next graph replay
        }
    }
}

// ---------------- pass 2: STARFM partial kernel ----------------
// one (bc, t, dy-half) slab per CTA; half 0: dy 0..7, half 1: dy 8..14
#define TOX 32
#define TOY 16            // tile 32x16 outputs; 256 threads x 2 outputs each
#define SMW (TOX + 14)    // 46
#define SMHMAX 23         // 15 + max(LH) = 15 + 8

__device__ __forceinline__ void acc_one(float4 q, float pf,
                                        float spat, float ms, float mt,
                                        float pfc, float thr,
                                        float& S0, float& S1)
{
    float den = fmaf(q.z, spat, EPSF);
    float w;
    asm("rcp.approx.f32 %0, %1;" : "=f"(w) : "f"(den));
    float d = pf - pfc;                                        // NaN-propagating
    int pass = (q.x < ms) & (q.y < mt) & (fabsf(d) < thr);     // NaN -> false
    w = pass ? w : 0.0f;
    S0 += w;
    S1 = fmaf(w, q.w, S1);
}

__global__ __launch_bounds__(256, 4)
void starfm_kernel()
{
    __shared__ float4 Sq[SMHMAX][SMW];
    __shared__ float  Spf[SMHMAX][SMW];

    const int z    = blockIdx.z;          // 0..31
    const int pz   = z & 15;              // plane = bc*2 + t
    const int half = z >> 4;              // 0 or 1
    const int bc   = pz >> 1;
    const int dbase = half * 8;
    const int LH    = half ? 7 : 8;       // #dy rows in this half
    const int rows  = 15 + LH;            // staged tile height

    const int ty0 = blockIdx.y * TOY;
    const int tx0 = blockIdx.x * TOX;
    const int tx  = threadIdx.x, ty = threadIdx.y;   // block (32, 8)
    const int tid = ty * 32 + tx;

    const float thr = g_thr;

    // stage this slab's tile
    {
        const int pbase = pz * NPIX;
        for (int i = tid; i < rows * SMW; i += 256) {
            int r  = i / SMW;
            int cl = i - r * SMW;
            int g  = pbase + (ty0 + dbase + r) * W_IMG + (tx0 + cl);
            Sq[r][cl]  = g_q[g];
            Spf[r][cl] = g_pfn[g];
        }
    }

    // center data: ms/mt need max over BOTH t planes; pfc own-t only
    float ms[2], mt[2], pfc[2];
    #pragma unroll
    for (int o = 0; o < 2; ++o) {
        int cpix = (ty0 + 2 * ty + o + 7) * W_IMG + (tx0 + tx + 7);
        float4 q0 = g_q[(bc * 2 + 0) * NPIX + cpix];
        float4 q1 = g_q[(bc * 2 + 1) * NPIX + cpix];
        ms[o]  = fmaxf(q0.x, q1.x) + SPEC_U;
        mt[o]  = fmaxf(q0.y, q1.y) + TEMP_U;
        pfc[o] = g_pfn[pz * NPIX + cpix];
    }
    __syncthreads();

    float S0a = 0.f, S1a = 0.f, S0b = 0.f, S1b = 0.f;
    const int row0 = 2 * ty;

    // ---- rr = 0: output 0 only (dy = dbase) ----
    {
        int d0 = dbase - 7;
        float base0 = fmaf((float)(d0 * d0), 1.0f / 7.0f, 1.0f);
        const float4* rq  = &Sq[row0][tx];
        const float*  rpf = &Spf[row0][tx];
        #pragma unroll
        for (int dx = 0; dx < 15; ++dx) {
            const float cadd = (float)((dx - 7) * (dx - 7)) * (1.0f / 7.0f);
            acc_one(rq[dx], rpf[dx], base0 + cadd, ms[0], mt[0], pfc[0], thr, S0a, S1a);
        }
    }
    // ---- rr = 1..LH-1: both outputs (out0 dy=dbase+rr, out1 dy=dbase+rr-1) --
    #pragma unroll 1
    for (int rr = 1; rr < LH; ++rr) {
        int d0 = dbase + rr - 7, d1 = dbase + rr - 8;
        float base0 = fmaf((float)(d0 * d0), 1.0f / 7.0f, 1.0f);
        float base1 = fmaf((float)(d1 * d1), 1.0f / 7.0f, 1.0f);
        const float4* rq  = &Sq[row0 + rr][tx];
        const float*  rpf = &Spf[row0 + rr][tx];
        #pragma unroll
        for (int dx = 0; dx < 15; ++dx) {
            const float cadd = (float)((dx - 7) * (dx - 7)) * (1.0f / 7.0f);
            float4 q = rq[dx];
            float pf = rpf[dx];
            acc_one(q, pf, base0 + cadd, ms[0], mt[0], pfc[0], thr, S0a, S1a);
            acc_one(q, pf, base1 + cadd, ms[1], mt[1], pfc[1], thr, S0b, S1b);
        }
    }
    // ---- rr = LH: output 1 only (dy = dbase + LH - 1) ----
    {
        int d1 = dbase + LH - 8;
        float base1 = fmaf((float)(d1 * d1), 1.0f / 7.0f, 1.0f);
        const float4* rq  = &Sq[row0 + LH][tx];
        const float*  rpf = &Spf[row0 + LH][tx];
        #pragma unroll
        for (int dx = 0; dx < 15; ++dx) {
            const float cadd = (float)((dx - 7) * (dx - 7)) * (1.0f / 7.0f);
            acc_one(rq[dx], rpf[dx], base1 + cadd, ms[1], mt[1], pfc[1], thr, S0b, S1b);
        }
    }

    const int oy0 = ty0 + 2 * ty, ox = tx0 + tx;
    float2* ps = g_ps[half * NPLANE + pz];
    ps[(oy0 + 0) * OHW + ox] = make_float2(S0a, S1a);
    ps[(oy0 + 1) * OHW + ox] = make_float2(S0b, S1b);
}

// ---------------- pass 3: combine partials ----------------
__global__ __launch_bounds__(256)
void combine_kernel(float* __restrict__ out)
{
    int i = blockIdx.x * blockDim.x + threadIdx.x;    // 0 .. NBC*NOUT-1
    if (i >= NBC * NOUT) return;
    int bc  = i / NOUT;
    int pix = i - bc * NOUT;
    float2 a0 = g_ps[bc * 2 + 0][pix];
    float2 a1 = g_ps[bc * 2 + 1][pix];
    float2 b0 = g_ps[NPLANE + bc * 2 + 0][pix];
    float2 b1 = g_ps[NPLANE + bc * 2 + 1][pix];
    float S0 = ((a0.x + a1.x) + (b0.x + b1.x));
    float S1 = ((a0.y + a1.y) + (b0.y + b1.y));
    out[i] = S1 / (S0 + EPSF);
}

// ---------------- launch ----------------
extern "C" void kernel_launch(void* const* d_in, const int* in_sizes, int n_in,
                              void* d_out, int out_size)
{
    const float* pc = (const float*)d_in[0];   // prior_coarse (2,4,2,110,110)
    const float* pf = (const float*)d_in[1];   // prior_fine   (2,4,2,110,110)
    const float* pd = (const float*)d_in[2];   // pred_coarse  (2,4,110,110)
    float* out = (float*)d_out;                // (2,4,96,96)

    prep_kernel<<<PREP_BLOCKS, PREP_THREADS>>>(pc, pf, pd);

    dim3 grid(OHW / TOX, OHW / TOY, 2 * NPLANE);   // (3, 6, 32) = 576 CTAs
    dim3 block(32, 8);
    starfm_kernel<<<grid, block>>>();

    combine_kernel<<<(NBC * NOUT + 255) / 256, 256>>>(out);
}

// round 7
// speedup vs baseline: 1.0069x; 1.0069x over previous
#include <cuda_runtime.h>
#include <math.h>

// ---------------- problem constants ----------------
#define H_IMG 110
#define W_IMG 110
#define NPIX  (H_IMG * W_IMG)      // 12100
#define OHW   96
#define NOUT  (OHW * OHW)          // 9216
#define NBC   8                    // b*c = 2*4
#define NPLANE (NBC * 2)           // 16 (bc, t)
#define EPSF  1e-8f
#define SPEC_U 1.4142135623730951e-3f
#define TEMP_U 1.4142135623730951e-3f

// ---------------- scratch (static: no allocation allowed) ----------------
__device__ float4 g_q[NPLANE * NPIX];    // (spec, temp, G, val)
__device__ float  g_pfn[NPLANE * NPIX];  // pf if valid else NaN
__device__ float  g_thr;
__device__ float2 g_ps[NPLANE][NOUT];    // per-(bc,t) partial (S0, S1)

#define PREP_THREADS 256
#define PREP_BLOCKS  ((NPLANE * NPIX + PREP_THREADS - 1) / PREP_THREADS)  // 757
__device__ float g_part[PREP_BLOCKS][3];
__device__ unsigned int g_ticket = 0;

__device__ __forceinline__ int wcount(int i) {   // #windows covering index i
    int lo = i - 14; if (lo < 0) lo = 0;
    int hi = i;      if (hi > 95) hi = 95;
    return hi - lo + 1;
}

__device__ __forceinline__ float warp_redf(float v) {
    #pragma unroll
    for (int o = 16; o > 0; o >>= 1) v += __shfl_down_sync(0xffffffffu, v, o);
    return v;
}
__device__ __forceinline__ double warp_redd(double v) {
    #pragma unroll
    for (int o = 16; o > 0; o >>= 1) v += __shfl_down_sync(0xffffffffu, v, o);
    return v;
}

// ---------------- pass 1: per-pixel precompute + fused thr reduction --------
__global__ __launch_bounds__(PREP_THREADS)
void prep_kernel(const float* __restrict__ pcg,
                 const float* __restrict__ pfg,
                 const float* __restrict__ pdg)
{
    const int idx = blockIdx.x * blockDim.x + threadIdx.x;
    float c = 0.f, s = 0.f, s2 = 0.f;
    if (idx < NPLANE * NPIX) {
        int p   = idx / NPIX;
        int pix = idx - p * NPIX;
        float vpc = pcg[idx];
        float vpf = pfg[idx];
        float vpd = pdg[(p >> 1) * NPIX + pix];

        float spec = fabsf(vpc - vpf);
        float temp = fabsf(vpc - vpd);
        float G    = logf(spec + 1.0f) * logf(temp + 1.0f);
        float val  = (vpd + vpf) - vpc;

        g_q[idx]   = make_float4(spec, temp, G, val);
        g_pfn[idx] = (vpf >= EPSF) ? vpf : __int_as_float(0x7fffffff); // NaN

        if (vpf >= EPSF) {
            int h = pix / W_IMG, w = pix - h * W_IMG;
            float mult = (float)(wcount(h) * wcount(w));
            c  = mult;
            s  = mult * vpf;
            s2 = s * vpf;
        }
    }

    __shared__ float  smf[8][3];
    __shared__ double smd[8][3];
    __shared__ int isLast;
    const int tid = threadIdx.x, warp = tid >> 5, lane = tid & 31;
    c = warp_redf(c); s = warp_redf(s); s2 = warp_redf(s2);
    if (lane == 0) { smf[warp][0] = c; smf[warp][1] = s; smf[warp][2] = s2; }
    __syncthreads();
    if (tid == 0) {
        float C = 0, S = 0, S2 = 0;
        #pragma unroll
        for (int w = 0; w < 8; w++) { C += smf[w][0]; S += smf[w][1]; S2 += smf[w][2]; }
        g_part[blockIdx.x][0] = C; g_part[blockIdx.x][1] = S; g_part[blockIdx.x][2] = S2;
        __threadfence();
        unsigned t = atomicAdd(&g_ticket, 1u);
        isLast = (t == gridDim.x - 1);
    }
    __syncthreads();
    if (isLast) {
        __threadfence();
        double cc = 0, ss = 0, ss2 = 0;
        for (int i = tid; i < PREP_BLOCKS; i += PREP_THREADS) {   // fixed order
            cc  += (double)g_part[i][0];
            ss  += (double)g_part[i][1];
            ss2 += (double)g_part[i][2];
        }
        cc = warp_redd(cc); ss = warp_redd(ss); ss2 = warp_redd(ss2);
        if (lane == 0) { smd[warp][0] = cc; smd[warp][1] = ss; smd[warp][2] = ss2; }
        __syncthreads();
        if (tid == 0) {
            double C = 0, S = 0, S2 = 0;
            #pragma unroll
            for (int w = 0; w < 8; w++) { C += smd[w][0]; S += smd[w][1]; S2 += smd[w][2]; }
            double m = S / C, m2 = S2 / C;
            g_thr = (float)(2.0 * sqrt(m2 - m * m) / 5.0);
            g_ticket = 0;     // reset for next graph replay
        }
    }
}

// ---------------- pass 2: STARFM partial kernel ----------------
// one (bc, t) plane per CTA; tile 32x32 outputs; 256 threads x 4 outputs each
#define TOX 32
#define TOY 32
#define SMW (TOX + 14)    // 46
#define SMH (TOY + 14)    // 46

__device__ __forceinline__ void acc_one(float4 q, float pf,
                                        float spat, float ms, float mt,
                                        float pfc, float thr,
                                        float& S0, float& S1)
{
    float den = fmaf(q.z, spat, EPSF);
    float w;
    asm("rcp.approx.f32 %0, %1;" : "=f"(w) : "f"(den));
    float d = pf - pfc;                                        // NaN-propagating
    int pass = (q.x < ms) & (q.y < mt) & (fabsf(d) < thr);     // NaN -> false
    w = pass ? w : 0.0f;
    S0 += w;
    S1 = fmaf(w, q.w, S1);
}

// accumulate one staged row r into outputs o = OMIN..OMAX (dy = r - o)
template<int OMIN, int OMAX>
__device__ __forceinline__ void row_acc(const float4* __restrict__ rq,
                                        const float*  __restrict__ rpf,
                                        int r,
                                        const float* ms, const float* mt,
                                        const float* pfc, float thr,
                                        float* S0, float* S1)
{
    float base[4];
    #pragma unroll
    for (int o = OMIN; o <= OMAX; ++o) {
        int d = (r - o) - 7;
        base[o] = fmaf((float)(d * d), 1.0f / 7.0f, 1.0f);
    }
    #pragma unroll
    for (int dx = 0; dx < 15; ++dx) {
        const float cadd = (float)((dx - 7) * (dx - 7)) * (1.0f / 7.0f);
        float4 q = rq[dx];
        float pf = rpf[dx];
        #pragma unroll
        for (int o = OMIN; o <= OMAX; ++o)
            acc_one(q, pf, base[o] + cadd, ms[o], mt[o], pfc[o], thr, S0[o], S1[o]);
    }
}

__global__ __launch_bounds__(256)
void starfm_kernel()
{
    __shared__ float4 Sq[SMH][SMW];
    __shared__ float  Spf[SMH][SMW];

    const int pz  = blockIdx.z;           // plane = bc*2 + t
    const int bc  = pz >> 1;
    const int ty0 = blockIdx.y * TOY;
    const int tx0 = blockIdx.x * TOX;
    const int tx  = threadIdx.x, ty = threadIdx.y;   // block (32, 8)
    const int tid = ty * 32 + tx;

    const float thr = g_thr;

    // stage this plane's 46x46 tile
    {
        const int pbase = pz * NPIX;
        for (int i = tid; i < SMH * SMW; i += 256) {
            int r  = i / SMW;
            int cl = i - r * SMW;
            int g  = pbase + (ty0 + r) * W_IMG + (tx0 + cl);
            Sq[r][cl]  = g_q[g];
            Spf[r][cl] = g_pfn[g];
        }
    }

    // center data for 4 outputs (rows 4*ty + o); ms/mt = max over both t planes
    const int row0 = 4 * ty;
    float ms[4], mt[4], pfc[4];
    #pragma unroll
    for (int o = 0; o < 4; ++o) {
        int cpix = (ty0 + row0 + o + 7) * W_IMG + (tx0 + tx + 7);
        float4 q0 = g_q[(bc * 2 + 0) * NPIX + cpix];
        float4 q1 = g_q[(bc * 2 + 1) * NPIX + cpix];
        ms[o]  = fmaxf(q0.x, q1.x) + SPEC_U;
        mt[o]  = fmaxf(q0.y, q1.y) + TEMP_U;
        pfc[o] = g_pfn[pz * NPIX + cpix];
    }
    __syncthreads();

    float S0[4] = {0.f, 0.f, 0.f, 0.f};
    float S1[4] = {0.f, 0.f, 0.f, 0.f};

    // staged row r (tile-relative row0 + r) serves outputs o in [max(0,r-14), min(3,r)]
    #define ROWPTRS(r) const float4* rq = &Sq[row0 + (r)][tx]; \
                       const float*  rpf = &Spf[row0 + (r)][tx];
    { ROWPTRS(0)  row_acc<0,0>(rq, rpf, 0,  ms, mt, pfc, thr, S0, S1); }
    { ROWPTRS(1)  row_acc<0,1>(rq, rpf, 1,  ms, mt, pfc, thr, S0, S1); }
    { ROWPTRS(2)  row_acc<0,2>(rq, rpf, 2,  ms, mt, pfc, thr, S0, S1); }
    #pragma unroll 1
    for (int r = 3; r < 15; ++r) {
        ROWPTRS(r)
        row_acc<0,3>(rq, rpf, r, ms, mt, pfc, thr, S0, S1);
    }
    { ROWPTRS(15) row_acc<1,3>(rq, rpf, 15, ms, mt, pfc, thr, S0, S1); }
    { ROWPTRS(16) row_acc<2,3>(rq, rpf, 16, ms, mt, pfc, thr, S0, S1); }
    { ROWPTRS(17) row_acc<3,3>(rq, rpf, 17, ms, mt, pfc, thr, S0, S1); }
    #undef ROWPTRS

    const int ox = tx0 + tx;
    #pragma unroll
    for (int o = 0; o < 4; ++o) {
        int oy = ty0 + row0 + o;
        g_ps[pz][oy * OHW + ox] = make_float2(S0[o], S1[o]);
    }
}

// ---------------- pass 3: combine t-partials ----------------
__global__ __launch_bounds__(256)
void combine_kernel(float* __restrict__ out)
{
    int i = blockIdx.x * blockDim.x + threadIdx.x;    // 0 .. NBC*NOUT-1
    if (i >= NBC * NOUT) return;
    int bc  = i / NOUT;
    int pix = i - bc * NOUT;
    float2 a = g_ps[bc * 2 + 0][pix];
    float2 b = g_ps[bc * 2 + 1][pix];
    out[i] = (a.y + b.y) / ((a.x + b.x) + EPSF);
}

// ---------------- launch ----------------
extern "C" void kernel_launch(void* const* d_in, const int* in_sizes, int n_in,
                              void* d_out, int out_size)
{
    const float* pc = (const float*)d_in[0];   // prior_coarse (2,4,2,110,110)
    const float* pf = (const float*)d_in[1];   // prior_fine   (2,4,2,110,110)
    const float* pd = (const float*)d_in[2];   // pred_coarse  (2,4,110,110)
    float* out = (float*)d_out;                // (2,4,96,96)

    prep_kernel<<<PREP_BLOCKS, PREP_THREADS>>>(pc, pf, pd);

    dim3 grid(OHW / TOX, OHW / TOY, NPLANE);   // (3, 3, 16) = 144 CTAs
    dim3 block(32, 8);
    starfm_kernel<<<grid, block>>>();

    combine_kernel<<<(NBC * NOUT + 255) / 256, 256>>>(out);
}

// round 8
// speedup vs baseline: 1.3990x; 1.3895x over previous
#include <cuda_runtime.h>
#include <math.h>

// ---------------- problem constants ----------------
#define H_IMG 110
#define W_IMG 110
#define NPIX  (H_IMG * W_IMG)      // 12100
#define OHW   96
#define NOUT  (OHW * OHW)          // 9216
#define NBC   8                    // b*c = 2*4
#define NPLANE (NBC * 2)           // 16 (bc, t)
#define EPSF  1e-8f
#define SPEC_U 1.4142135623730951e-3f
#define TEMP_U 1.4142135623730951e-3f

// ---------------- scratch (static: no allocation allowed) ----------------
__device__ float4 g_q[NPLANE * NPIX];     // (spec, temp, R=1/(G+eps), val)
__device__ float  g_pfn[NPLANE * NPIX];   // pf if valid else NaN
__device__ float  g_thr;
__device__ float2 g_ps[2 * NPLANE][NOUT]; // per-(xhalf, plane) partial (S0, S1)

#define PREP_THREADS 256
#define PREP_PPT     8             // pixels per thread
#define PREP_BLOCKS  ((NPLANE * NPIX + PREP_THREADS * PREP_PPT - 1) / (PREP_THREADS * PREP_PPT)) // 95
__device__ float g_part[PREP_BLOCKS][3];
__device__ unsigned int g_ticket = 0;

__device__ __forceinline__ int wcount(int i) {   // #windows covering index i
    int lo = i - 14; if (lo < 0) lo = 0;
    int hi = i;      if (hi > 95) hi = 95;
    return hi - lo + 1;
}

__device__ __forceinline__ float warp_redf(float v) {
    #pragma unroll
    for (int o = 16; o > 0; o >>= 1) v += __shfl_down_sync(0xffffffffu, v, o);
    return v;
}
__device__ __forceinline__ double warp_redd(double v) {
    #pragma unroll
    for (int o = 16; o > 0; o >>= 1) v += __shfl_down_sync(0xffffffffu, v, o);
    return v;
}

// ---------------- pass 1: per-pixel precompute + fused thr reduction --------
__device__ __forceinline__ void prep_one(float vpc, float vpf, float vpd,
                                         int idx, int pix,
                                         float& c, float& s, float& s2)
{
    float spec = fabsf(vpc - vpf);
    float temp = fabsf(vpc - vpd);
    float G    = logf(spec + 1.0f) * logf(temp + 1.0f);
    float R    = 1.0f / (G + EPSF);
    float val  = (vpd + vpf) - vpc;

    g_q[idx]   = make_float4(spec, temp, R, val);
    g_pfn[idx] = (vpf >= EPSF) ? vpf : __int_as_float(0x7fffffff); // NaN

    if (vpf >= EPSF) {
        int h = pix / W_IMG, w = pix - h * W_IMG;
        float mult = (float)(wcount(h) * wcount(w));
        c  += mult;
        s  += mult * vpf;
        s2 += mult * vpf * vpf;
    }
}

__global__ __launch_bounds__(PREP_THREADS)
void prep_kernel(const float* __restrict__ pcg,
                 const float* __restrict__ pfg,
                 const float* __restrict__ pdg)
{
    const int g0 = (blockIdx.x * blockDim.x + threadIdx.x) * PREP_PPT;
    float c = 0.f, s = 0.f, s2 = 0.f;

    #pragma unroll
    for (int grp = 0; grp < PREP_PPT / 4; ++grp) {
        int idx = g0 + grp * 4;                 // 4-aligned; NPIX % 4 == 0
        if (idx < NPLANE * NPIX) {
            int p   = idx / NPIX;
            int pix = idx - p * NPIX;
            float4 a = *(const float4*)(pcg + idx);
            float4 f = *(const float4*)(pfg + idx);
            float4 d = *(const float4*)(pdg + (p >> 1) * NPIX + pix);
            prep_one(a.x, f.x, d.x, idx + 0, pix + 0, c, s, s2);
            prep_one(a.y, f.y, d.y, idx + 1, pix + 1, c, s, s2);
            prep_one(a.z, f.z, d.z, idx + 2, pix + 2, c, s, s2);
            prep_one(a.w, f.w, d.w, idx + 3, pix + 3, c, s, s2);
        }
    }

    __shared__ float  smf[8][3];
    __shared__ double smd[8][3];
    __shared__ int isLast;
    const int tid = threadIdx.x, warp = tid >> 5, lane = tid & 31;
    c = warp_redf(c); s = warp_redf(s); s2 = warp_redf(s2);
    if (lane == 0) { smf[warp][0] = c; smf[warp][1] = s; smf[warp][2] = s2; }
    __syncthreads();
    if (tid == 0) {
        float C = 0, S = 0, S2 = 0;
        #pragma unroll
        for (int w = 0; w < 8; w++) { C += smf[w][0]; S += smf[w][1]; S2 += smf[w][2]; }
        g_part[blockIdx.x][0] = C; g_part[blockIdx.x][1] = S; g_part[blockIdx.x][2] = S2;
        __threadfence();
        unsigned t = atomicAdd(&g_ticket, 1u);
        isLast = (t == gridDim.x - 1);
    }
    __syncthreads();
    if (isLast) {
        __threadfence();
        double cc = 0, ss = 0, ss2 = 0;
        for (int i = tid; i < PREP_BLOCKS; i += PREP_THREADS) {   // fixed order
            cc  += (double)g_part[i][0];
            ss  += (double)g_part[i][1];
            ss2 += (double)g_part[i][2];
        }
        cc = warp_redd(cc); ss = warp_redd(ss); ss2 = warp_redd(ss2);
        if (lane == 0) { smd[warp][0] = cc; smd[warp][1] = ss; smd[warp][2] = ss2; }
        __syncthreads();
        if (tid == 0) {
            double C = 0, S = 0, S2 = 0;
            #pragma unroll
            for (int w = 0; w < 8; w++) { C += smd[w][0]; S += smd[w][1]; S2 += smd[w][2]; }
            double m = S / C, m2 = S2 / C;
            g_thr = (float)(2.0 * sqrt(m2 - m * m) / 5.0);
            g_ticket = 0;     // reset for next graph replay
        }
    }
}

// ---------------- pass 2: STARFM partial kernel ----------------
// one (plane, dx-half) per CTA; tile 32x32 outputs; 256 threads x 4 outputs each
#define TOX 32
#define TOY 32
#define SMWX 40           // staged cols (32 + 8 dx, padded)
#define SMH 46            // staged rows (32 + 14)

// accumulate staged row rr into outputs o = OMIN..OMAX (dy = rr - o)
template<int OMIN, int OMAX>
__device__ __forceinline__ void row_acc(const float4* __restrict__ rq,
                                        const float*  __restrict__ rpf,
                                        const float (*__restrict__ Sinv)[16],
                                        int rr, int dxlo,
                                        const float* ms, const float* mt,
                                        const float* lo, const float* hi,
                                        float* S0, float* S1)
{
    #pragma unroll
    for (int j = 0; j < 8; ++j) {
        float4 q = rq[j];
        float pf = rpf[j];
        #pragma unroll
        for (int o = OMIN; o <= OMAX; ++o) {
            float inv = Sinv[rr - o][dxlo + j];   // uniform LDS broadcast
            float w = q.z * inv;                  // 0 for phantom dx=15
            bool pass = (q.x < ms[o]) & (q.y < mt[o]) &
                        (pf > lo[o]) & (pf < hi[o]);     // NaN -> false
            if (pass) {
                S0[o] += w;
                S1[o] = fmaf(w, q.w, S1[o]);
            }
        }
    }
}

__global__ __launch_bounds__(256, 2)
void starfm_kernel()
{
    __shared__ float4 Sq[SMH][SMWX];
    __shared__ float  Spf[SMH][SMWX];
    __shared__ float  Sinv[15][16];

    const int z     = blockIdx.z;          // 0..31
    const int pz    = z & 15;              // plane = bc*2 + t
    const int xhalf = z >> 4;              // 0 or 1
    const int bc    = pz >> 1;
    const int dxlo  = xhalf * 8;           // dx base (8..15 half: dx=15 phantom)

    const int ty0 = blockIdx.y * TOY;
    const int tx0 = blockIdx.x * TOX;
    const int tx  = threadIdx.x, ty = threadIdx.y;   // block (32, 8)
    const int tid = ty * 32 + tx;

    // invspat table: inv = 7/(d^2+7); phantom column dx=15 -> 0
    if (tid < 240) {
        int dy = tid >> 4, dx = tid & 15;
        float v = 0.0f;
        if (dx < 15) {
            int d2 = (dy - 7) * (dy - 7) + (dx - 7) * (dx - 7);
            v = 7.0f / (float)(d2 + 7);
        }
        Sinv[dy][dx] = v;
    }

    // stage tile: rows ty0..ty0+45, cols tx0+dxlo .. +SMWX-1 (clamped)
    {
        const int pbase = pz * NPIX;
        for (int i = tid; i < SMH * SMWX; i += 256) {
            int r  = i / SMWX;
            int cl = i - r * SMWX;
            int gx = tx0 + dxlo + cl; if (gx > 109) gx = 109;   // clamp OOB
            int g  = pbase + (ty0 + r) * W_IMG + gx;
            Sq[r][cl]  = g_q[g];
            Spf[r][cl] = g_pfn[g];
        }
    }

    const float thr = g_thr;

    // center data for 4 outputs (rows 4*ty + o); ms/mt = max over both t planes
    const int row0 = 4 * ty;
    float ms[4], mt[4], lo[4], hi[4];
    #pragma unroll
    for (int o = 0; o < 4; ++o) {
        int cpix = (ty0 + row0 + o + 7) * W_IMG + (tx0 + tx + 7);
        float4 q0 = g_q[(bc * 2 + 0) * NPIX + cpix];
        float4 q1 = g_q[(bc * 2 + 1) * NPIX + cpix];
        ms[o] = fmaxf(q0.x, q1.x) + SPEC_U;
        mt[o] = fmaxf(q0.y, q1.y) + TEMP_U;
        float pfc = g_pfn[pz * NPIX + cpix];     // may be NaN
        lo[o] = pfc - thr;
        hi[o] = pfc + thr;
    }
    __syncthreads();

    float S0[4] = {0.f, 0.f, 0.f, 0.f};
    float S1[4] = {0.f, 0.f, 0.f, 0.f};

    #define ROWPTRS(r) const float4* rq = &Sq[row0 + (r)][tx]; \
                       const float*  rpf = &Spf[row0 + (r)][tx];
    { ROWPTRS(0)  row_acc<0,0>(rq, rpf, Sinv, 0,  dxlo, ms, mt, lo, hi, S0, S1); }
    { ROWPTRS(1)  row_acc<0,1>(rq, rpf, Sinv, 1,  dxlo, ms, mt, lo, hi, S0, S1); }
    { ROWPTRS(2)  row_acc<0,2>(rq, rpf, Sinv, 2,  dxlo, ms, mt, lo, hi, S0, S1); }
    #pragma unroll 1
    for (int r = 3; r < 15; ++r) {
        ROWPTRS(r)
        row_acc<0,3>(rq, rpf, Sinv, r, dxlo, ms, mt, lo, hi, S0, S1);
    }
    { ROWPTRS(15) row_acc<1,3>(rq, rpf, Sinv, 15, dxlo, ms, mt, lo, hi, S0, S1); }
    { ROWPTRS(16) row_acc<2,3>(rq, rpf, Sinv, 16, dxlo, ms, mt, lo, hi, S0, S1); }
    { ROWPTRS(17) row_acc<3,3>(rq, rpf, Sinv, 17, dxlo, ms, mt, lo, hi, S0, S1); }
    #undef ROWPTRS

    const int ox = tx0 + tx;
    float2* ps = g_ps[xhalf * NPLANE + pz];
    #pragma unroll
    for (int o = 0; o < 4; ++o) {
        int oy = ty0 + row0 + o;
        ps[oy * OHW + ox] = make_float2(S0[o], S1[o]);
    }
}

// ---------------- pass 3: combine partials ----------------
__global__ __launch_bounds__(256)
void combine_kernel(float* __restrict__ out)
{
    int i = blockIdx.x * blockDim.x + threadIdx.x;    // 0 .. NBC*NOUT-1
    if (i >= NBC * NOUT) return;
    int bc  = i / NOUT;
    int pix = i - bc * NOUT;
    float2 a0 = g_ps[bc * 2 + 0][pix];
    float2 a1 = g_ps[bc * 2 + 1][pix];
    float2 b0 = g_ps[NPLANE + bc * 2 + 0][pix];
    float2 b1 = g_ps[NPLANE + bc * 2 + 1][pix];
    float S0 = (a0.x + a1.x) + (b0.x + b1.x);
    float S1 = (a0.y + a1.y) + (b0.y + b1.y);
    out[i] = S1 / (S0 + EPSF);
}

// ---------------- launch ----------------
extern "C" void kernel_launch(void* const* d_in, const int* in_sizes, int n_in,
                              void* d_out, int out_size)
{
    const float* pc = (const float*)d_in[0];   // prior_coarse (2,4,2,110,110)
    const float* pf = (const float*)d_in[1];   // prior_fine   (2,4,2,110,110)
    const float* pd = (const float*)d_in[2];   // pred_coarse  (2,4,110,110)
    float* out = (float*)d_out;                // (2,4,96,96)

    prep_kernel<<<PREP_BLOCKS, PREP_THREADS>>>(pc, pf, pd);

    dim3 grid(OHW / TOX, OHW / TOY, 2 * NPLANE);   // (3, 3, 32) = 288 CTAs
    dim3 block(32, 8);
    starfm_kernel<<<grid, block>>>();

    combine_kernel<<<(NBC * NOUT + 255) / 256, 256>>>(out);
}

// round 10
// speedup vs baseline: 1.4842x; 1.0608x over previous
#include <cuda_runtime.h>
#include <math.h>

// ---------------- problem constants ----------------
#define H_IMG 110
#define W_IMG 110
#define NPIX  (H_IMG * W_IMG)      // 12100
#define OHW   96
#define NOUT  (OHW * OHW)          // 9216
#define NBC   8                    // b*c = 2*4
#define NPLANE (NBC * 2)           // 16 (bc, t)
#define EPSF  1e-8f
#define SPEC_U 1.4142135623730951e-3f
#define TEMP_U 1.4142135623730951e-3f

// ---------------- scratch (static: no allocation allowed) ----------------
__device__ float4 g_q[NPLANE * NPIX];     // (spec, temp, R=1/(G+eps), val)
__device__ float  g_pfn[NPLANE * NPIX];   // pf if valid else NaN
__device__ float  g_thr;
__device__ float2 g_ps[NPLANE][NOUT];     // per-(bc,t) partial (S0, S1)

#define PREP_THREADS 256
#define PREP_PPT     2             // pixels per thread
#define PREP_BLOCKS  ((NPLANE * NPIX + PREP_THREADS * PREP_PPT - 1) / (PREP_THREADS * PREP_PPT)) // 379
__device__ float g_part[PREP_BLOCKS][3];
__device__ unsigned int g_ticket = 0;

__device__ __forceinline__ int wcount(int i) {   // #windows covering index i
    int lo = i - 14; if (lo < 0) lo = 0;
    int hi = i;      if (hi > 95) hi = 95;
    return hi - lo + 1;
}

__device__ __forceinline__ float warp_redf(float v) {
    #pragma unroll
    for (int o = 16; o > 0; o >>= 1) v += __shfl_down_sync(0xffffffffu, v, o);
    return v;
}
__device__ __forceinline__ double warp_redd(double v) {
    #pragma unroll
    for (int o = 16; o > 0; o >>= 1) v += __shfl_down_sync(0xffffffffu, v, o);
    return v;
}

// log(fl(1+x))/2 via atanh form; rel err ~4e-7, matches reference arg rounding
__device__ __forceinline__ float log1p_half(float x) {
    float u   = 1.0f + x;        // same rounding as reference's (x + 1.0)
    float xp  = u - 1.0f;        // exact (u in [1,2])
    float up1 = u + 1.0f;
    float ri;
    asm("rcp.approx.f32 %0, %1;" : "=f"(ri) : "f"(up1));
    float z  = xp * ri;          // z in [0, 1/3]
    float z2 = z * z;
    float p  = fmaf(z2, 0.0909090909f, 0.1111111111f);  // 1/11, 1/9
    p = fmaf(p, z2, 0.1428571429f);                      // 1/7
    p = fmaf(p, z2, 0.2f);                               // 1/5
    p = fmaf(p, z2, 0.3333333333f);                      // 1/3
    p = fmaf(p, z2, 1.0f);
    return z * p;                // = atanh(z) = log(u)/2
}

// ---------------- pass 1: per-pixel precompute + fused thr reduction --------
__device__ __forceinline__ void prep_one(float vpc, float vpf, float vpd,
                                         int idx, int pix,
                                         float& c, float& s, float& s2)
{
    float spec = fabsf(vpc - vpf);
    float temp = fabsf(vpc - vpd);
    float l1 = log1p_half(spec);
    float l2 = log1p_half(temp);
    float G  = (l1 * l2) * 4.0f;
    float R;
    asm("rcp.approx.f32 %0, %1;" : "=f"(R) : "f"(G + EPSF));
    float val  = (vpd + vpf) - vpc;

    g_q[idx]   = make_float4(spec, temp, R, val);
    g_pfn[idx] = (vpf >= EPSF) ? vpf : __int_as_float(0x7fffffff); // NaN

    if (vpf >= EPSF) {
        int h = pix / W_IMG, w = pix - h * W_IMG;
        float mult = (float)(wcount(h) * wcount(w));
        c  += mult;
        s  += mult * vpf;
        s2 += mult * vpf * vpf;
    }
}

__global__ __launch_bounds__(PREP_THREADS)
void prep_kernel(const float* __restrict__ pcg,
                 const float* __restrict__ pfg,
                 const float* __restrict__ pdg)
{
    const int idx = (blockIdx.x * blockDim.x + threadIdx.x) * 2;
    float c = 0.f, s = 0.f, s2 = 0.f;

    if (idx < NPLANE * NPIX) {     // NPIX even: pair never crosses plane edge
        int p   = idx / NPIX;
        int pix = idx - p * NPIX;
        float2 a = *(const float2*)(pcg + idx);
        float2 f = *(const float2*)(pfg + idx);
        float2 d = *(const float2*)(pdg + (p >> 1) * NPIX + pix);
        prep_one(a.x, f.x, d.x, idx + 0, pix + 0, c, s, s2);
        prep_one(a.y, f.y, d.y, idx + 1, pix + 1, c, s, s2);
    }

    __shared__ float  smf[8][3];
    __shared__ double smd[8][3];
    __shared__ int isLast;
    const int tid = threadIdx.x, warp = tid >> 5, lane = tid & 31;
    c = warp_redf(c); s = warp_redf(s); s2 = warp_redf(s2);
    if (lane == 0) { smf[warp][0] = c; smf[warp][1] = s; smf[warp][2] = s2; }
    __syncthreads();
    if (tid == 0) {
        float C = 0, S = 0, S2 = 0;
        #pragma unroll
        for (int w = 0; w < 8; w++) { C += smf[w][0]; S += smf[w][1]; S2 += smf[w][2]; }
        g_part[blockIdx.x][0] = C; g_part[blockIdx.x][1] = S; g_part[blockIdx.x][2] = S2;
        __threadfence();
        unsigned t = atomicAdd(&g_ticket, 1u);
        isLast = (t == gridDim.x - 1);
    }
    __syncthreads();
    if (isLast) {
        __threadfence();
        double cc = 0, ss = 0, ss2 = 0;
        for (int i = tid; i < PREP_BLOCKS; i += PREP_THREADS) {   // fixed order
            cc  += (double)g_part[i][0];
            ss  += (double)g_part[i][1];
            ss2 += (double)g_part[i][2];
        }
        cc = warp_redd(cc); ss = warp_redd(ss); ss2 = warp_redd(ss2);
        if (lane == 0) { smd[warp][0] = cc; smd[warp][1] = ss; smd[warp][2] = ss2; }
        __syncthreads();
        if (tid == 0) {
            double C = 0, S = 0, S2 = 0;
            #pragma unroll
            for (int w = 0; w < 8; w++) { C += smd[w][0]; S += smd[w][1]; S2 += smd[w][2]; }
            double m = S / C, m2 = S2 / C;
            g_thr = (float)(2.0 * sqrt(m2 - m * m) / 5.0);
            g_ticket = 0;     // reset for next graph replay
        }
    }
}

// invspat = 7/(d^2+7); __host__ __device__ constexpr so device code may call it;
// after full unroll all args are constants and LLVM folds this to an immediate.
__host__ __device__ constexpr float inv_v(int dy, int dx) {
    return 7.0f / (float)((dy - 7) * (dy - 7) + (dx - 7) * (dx - 7) + 7);
}

// ---------------- pass 2: STARFM partial kernel ----------------
// one (bc,t) plane per CTA; tile 32x16 outputs; 256 threads x 2 outputs each
#define TOX 32
#define TOY 16
#define SMW (TOX + 14)    // 46
#define SMH (TOY + 14)    // 30

// staged row RR serves outputs o in [OMIN, OMAX]; dy = RR - o (compile-time)
template<int RR, int OMIN, int OMAX>
__device__ __forceinline__ void do_row(const float4* __restrict__ rq,
                                       const float*  __restrict__ rpf,
                                       const float* ms, const float* mt,
                                       const float* lo, const float* hi,
                                       float* S0, float* S1)
{
    #pragma unroll
    for (int dx = 0; dx < 15; ++dx) {
        float4 q = rq[dx];
        float pf = rpf[dx];
        #pragma unroll
        for (int o = OMIN; o <= OMAX; ++o) {
            float w = q.z * inv_v(RR - o, dx);      // immediate multiplier
            bool pass = (q.x < ms[o]) & (q.y < mt[o]) &
                        (pf > lo[o]) & (pf < hi[o]);     // NaN -> false
            if (pass) {
                S0[o] += w;
                S1[o] = fmaf(w, q.w, S1[o]);
            }
        }
    }
}

__global__ __launch_bounds__(256, 2)
void starfm_kernel()
{
    __shared__ float4 Sq[SMH][SMW];
    __shared__ float  Spf[SMH][SMW];

    const int pz  = blockIdx.z;           // plane = bc*2 + t
    const int bc  = pz >> 1;
    const int ty0 = blockIdx.y * TOY;
    const int tx0 = blockIdx.x * TOX;
    const int tx  = threadIdx.x, ty = threadIdx.y;   // block (32, 8)
    const int tid = ty * 32 + tx;

    // stage this plane's 30x46 tile
    {
        const int pbase = pz * NPIX;
        for (int i = tid; i < SMH * SMW; i += 256) {
            int r  = i / SMW;
            int cl = i - r * SMW;
            int g  = pbase + (ty0 + r) * W_IMG + (tx0 + cl);
            Sq[r][cl]  = g_q[g];
            Spf[r][cl] = g_pfn[g];
        }
    }

    const float thr = g_thr;

    // center data for 2 outputs (rows 2*ty + o); ms/mt = max over both t planes
    const int row0 = 2 * ty;
    float ms[2], mt[2], lo[2], hi[2];
    #pragma unroll
    for (int o = 0; o < 2; ++o) {
        int cpix = (ty0 + row0 + o + 7) * W_IMG + (tx0 + tx + 7);
        float4 q0 = g_q[(bc * 2 + 0) * NPIX + cpix];
        float4 q1 = g_q[(bc * 2 + 1) * NPIX + cpix];
        ms[o] = fmaxf(q0.x, q1.x) + SPEC_U;
        mt[o] = fmaxf(q0.y, q1.y) + TEMP_U;
        float pfc = g_pfn[pz * NPIX + cpix];     // may be NaN
        lo[o] = pfc - thr;
        hi[o] = pfc + thr;
    }
    __syncthreads();

    float S0[2] = {0.f, 0.f};
    float S1[2] = {0.f, 0.f};

    #define ROW(RR, A, B) do_row<RR, A, B>(&Sq[row0 + RR][tx], &Spf[row0 + RR][tx], \
                                           ms, mt, lo, hi, S0, S1);
    ROW(0,  0, 0)
    ROW(1,  0, 1)  ROW(2,  0, 1)  ROW(3,  0, 1)  ROW(4,  0, 1)
    ROW(5,  0, 1)  ROW(6,  0, 1)  ROW(7,  0, 1)  ROW(8,  0, 1)
    ROW(9,  0, 1)  ROW(10, 0, 1)  ROW(11, 0, 1)  ROW(12, 0, 1)
    ROW(13, 0, 1)  ROW(14, 0, 1)
    ROW(15, 1, 1)
    #undef ROW

    const int ox = tx0 + tx;
    #pragma unroll
    for (int o = 0; o < 2; ++o) {
        int oy = ty0 + row0 + o;
        g_ps[pz][oy * OHW + ox] = make_float2(S0[o], S1[o]);
    }
}

// ---------------- pass 3: combine t-partials ----------------
__global__ __launch_bounds__(256)
void combine_kernel(float* __restrict__ out)
{
    int i = blockIdx.x * blockDim.x + threadIdx.x;    // 0 .. NBC*NOUT-1
    if (i >= NBC * NOUT) return;
    int bc  = i / NOUT;
    int pix = i - bc * NOUT;
    float2 a = g_ps[bc * 2 + 0][pix];
    float2 b = g_ps[bc * 2 + 1][pix];
    out[i] = (a.y + b.y) / ((a.x + b.x) + EPSF);
}

// ---------------- launch ----------------
extern "C" void kernel_launch(void* const* d_in, const int* in_sizes, int n_in,
                              void* d_out, int out_size)
{
    const float* pc = (const float*)d_in[0];   // prior_coarse (2,4,2,110,110)
    const float* pf = (const float*)d_in[1];   // prior_fine   (2,4,2,110,110)
    const float* pd = (const float*)d_in[2];   // pred_coarse  (2,4,110,110)
    float* out = (float*)d_out;                // (2,4,96,96)

    prep_kernel<<<PREP_BLOCKS, PREP_THREADS>>>(pc, pf, pd);

    dim3 grid(OHW / TOX, OHW / TOY, NPLANE);   // (3, 6, 16) = 288 CTAs
    dim3 block(32, 8);
    starfm_kernel<<<grid, block>>>();

    combine_kernel<<<(NBC * NOUT + 255) / 256, 256>>>(out);
}

// round 11
// speedup vs baseline: 1.6041x; 1.0808x over previous
#include <cuda_runtime.h>
#include <math.h>

// ---------------- problem constants ----------------
#define H_IMG 110
#define W_IMG 110
#define NPIX  (H_IMG * W_IMG)      // 12100
#define OHW   96
#define NOUT  (OHW * OHW)          // 9216
#define NBC   8                    // b*c = 2*4
#define NPLANE (NBC * 2)           // 16 (bc, t)
#define EPSF  1e-8f
#define SPEC_U 1.4142135623730951e-3f
#define TEMP_U 1.4142135623730951e-3f

// ---------------- scratch (static: no allocation allowed) ----------------
__device__ float  g_thr;
__device__ float2 g_ps[NPLANE][NOUT];     // per-(bc,t) partial (S0, S1)

#define RED_THREADS 256
#define RED_PPT     4
#define RED_BLOCKS  ((NPLANE * NPIX + RED_THREADS * RED_PPT - 1) / (RED_THREADS * RED_PPT)) // 190
__device__ float g_part[RED_BLOCKS][3];
__device__ unsigned int g_ticket = 0;

__device__ __forceinline__ int wcount(int i) {   // #windows covering index i
    int lo = i - 14; if (lo < 0) lo = 0;
    int hi = i;      if (hi > 95) hi = 95;
    return hi - lo + 1;
}

__device__ __forceinline__ float warp_redf(float v) {
    #pragma unroll
    for (int o = 16; o > 0; o >>= 1) v += __shfl_down_sync(0xffffffffu, v, o);
    return v;
}
__device__ __forceinline__ double warp_redd(double v) {
    #pragma unroll
    for (int o = 16; o > 0; o >>= 1) v += __shfl_down_sync(0xffffffffu, v, o);
    return v;
}

// log(fl(1+x))/2 via atanh form; rel err ~4e-7, matches reference arg rounding
__device__ __forceinline__ float log1p_half(float x) {
    float u   = 1.0f + x;        // same rounding as reference's (x + 1.0)
    float xp  = u - 1.0f;        // exact (u in [1,2])
    float up1 = u + 1.0f;
    float ri;
    asm("rcp.approx.f32 %0, %1;" : "=f"(ri) : "f"(up1));
    float z  = xp * ri;          // z in [0, 1/3]
    float z2 = z * z;
    float p  = fmaf(z2, 0.0909090909f, 0.1111111111f);  // 1/11, 1/9
    p = fmaf(p, z2, 0.1428571429f);                      // 1/7
    p = fmaf(p, z2, 0.2f);                               // 1/5
    p = fmaf(p, z2, 0.3333333333f);                      // 1/3
    p = fmaf(p, z2, 1.0f);
    return z * p;                // = atanh(z) = log(u)/2
}

// ---------------- pass 1: thin thr reduction (reads pf only) ----------------
__global__ __launch_bounds__(RED_THREADS)
void reduce_kernel(const float* __restrict__ pfg)
{
    const int idx0 = (blockIdx.x * blockDim.x + threadIdx.x) * RED_PPT;
    float c = 0.f, s = 0.f, s2 = 0.f;

    if (idx0 < NPLANE * NPIX) {    // NPIX % 4 == 0: quad never crosses plane edge
        float4 f = *(const float4*)(pfg + idx0);
        #pragma unroll
        for (int j = 0; j < 4; ++j) {
            float vpf = j == 0 ? f.x : j == 1 ? f.y : j == 2 ? f.z : f.w;
            if (vpf >= EPSF) {
                int pix = (idx0 + j) % NPIX;
                int h = pix / W_IMG, w = pix - h * W_IMG;
                float mult = (float)(wcount(h) * wcount(w));
                c  += mult;
                s  += mult * vpf;
                s2 += mult * vpf * vpf;
            }
        }
    }

    __shared__ float  smf[8][3];
    __shared__ double smd[8][3];
    __shared__ int isLast;
    const int tid = threadIdx.x, warp = tid >> 5, lane = tid & 31;
    c = warp_redf(c); s = warp_redf(s); s2 = warp_redf(s2);
    if (lane == 0) { smf[warp][0] = c; smf[warp][1] = s; smf[warp][2] = s2; }
    __syncthreads();
    if (tid == 0) {
        float C = 0, S = 0, S2 = 0;
        #pragma unroll
        for (int w = 0; w < 8; w++) { C += smf[w][0]; S += smf[w][1]; S2 += smf[w][2]; }
        g_part[blockIdx.x][0] = C; g_part[blockIdx.x][1] = S; g_part[blockIdx.x][2] = S2;
        __threadfence();
        unsigned t = atomicAdd(&g_ticket, 1u);
        isLast = (t == gridDim.x - 1);
    }
    __syncthreads();
    if (isLast) {
        __threadfence();
        double cc = 0, ss = 0, ss2 = 0;
        for (int i = tid; i < RED_BLOCKS; i += RED_THREADS) {   // fixed order
            cc  += (double)g_part[i][0];
            ss  += (double)g_part[i][1];
            ss2 += (double)g_part[i][2];
        }
        cc = warp_redd(cc); ss = warp_redd(ss); ss2 = warp_redd(ss2);
        if (lane == 0) { smd[warp][0] = cc; smd[warp][1] = ss; smd[warp][2] = ss2; }
        __syncthreads();
        if (tid == 0) {
            double C = 0, S = 0, S2 = 0;
            #pragma unroll
            for (int w = 0; w < 8; w++) { C += smd[w][0]; S += smd[w][1]; S2 += smd[w][2]; }
            double m = S / C, m2 = S2 / C;
            g_thr = (float)(2.0 * sqrt(m2 - m * m) / 5.0);
            g_ticket = 0;     // reset for next graph replay
        }
    }
}

// invspat = 7/(d^2+7); constexpr folds to an immediate after full unroll
__host__ __device__ constexpr float inv_v(int dy, int dx) {
    return 7.0f / (float)((dy - 7) * (dy - 7) + (dx - 7) * (dx - 7) + 7);
}

// ---------------- pass 2: fused STARFM partial kernel ----------------
// one (bc,t) plane per CTA; tile 32x16 outputs; 256 threads x 2 outputs each
#define TOX 32
#define TOY 16
#define SMW (TOX + 14)    // 46
#define SMH (TOY + 14)    // 30

// staged row RR serves outputs o in [OMIN, OMAX]; dy = RR - o (compile-time)
template<int RR, int OMIN, int OMAX>
__device__ __forceinline__ void do_row(const float4* __restrict__ rq,
                                       const float*  __restrict__ rpf,
                                       const float* ms, const float* mt,
                                       const float* lo, const float* hi,
                                       float* S0, float* S1)
{
    #pragma unroll
    for (int dx = 0; dx < 15; ++dx) {
        float4 q = rq[dx];
        float pf = rpf[dx];
        #pragma unroll
        for (int o = OMIN; o <= OMAX; ++o) {
            float w = q.z * inv_v(RR - o, dx);      // immediate multiplier
            bool pass = (q.x < ms[o]) & (q.y < mt[o]) &
                        (pf > lo[o]) & (pf < hi[o]);     // NaN -> false
            if (pass) {
                S0[o] += w;
                S1[o] = fmaf(w, q.w, S1[o]);
            }
        }
    }
}

__global__ __launch_bounds__(256, 2)
void starfm_kernel(const float* __restrict__ pcg,
                   const float* __restrict__ pfg,
                   const float* __restrict__ pdg)
{
    __shared__ float4 Sq[SMH][SMW];
    __shared__ float  Spf[SMH][SMW];

    const int pz  = blockIdx.z;           // plane = bc*2 + t
    const int bc  = pz >> 1;
    const int ty0 = blockIdx.y * TOY;
    const int tx0 = blockIdx.x * TOX;
    const int tx  = threadIdx.x, ty = threadIdx.y;   // block (32, 8)
    const int tid = ty * 32 + tx;
    const int row0 = 2 * ty;

    const float* pcp = pcg + (size_t)pz * NPIX;
    const float* pfp = pfg + (size_t)pz * NPIX;
    const float* pdp = pdg + (size_t)bc * NPIX;

    // other-plane center spec/temp (raw LDGs issued early; latency hidden
    // under the staging loop below)
    const int oz = pz ^ 1;
    float osp[2], otp[2];
    #pragma unroll
    for (int o = 0; o < 2; ++o) {
        int cg = (ty0 + row0 + o + 7) * W_IMG + (tx0 + tx + 7);
        float c2 = pcg[(size_t)oz * NPIX + cg];
        float f2 = pfg[(size_t)oz * NPIX + cg];
        float d2 = pdp[cg];
        osp[o] = fabsf(c2 - f2);
        otp[o] = fabsf(c2 - d2);
    }

    // stage + inline per-pixel precompute (spec, temp, R, val, pfn)
    for (int i = tid; i < SMH * SMW; i += 256) {
        int r  = i / SMW;
        int cl = i - r * SMW;
        int g  = (ty0 + r) * W_IMG + (tx0 + cl);
        float vpc = pcp[g];
        float vpf = pfp[g];
        float vpd = pdp[g];
        float spec = fabsf(vpc - vpf);
        float temp = fabsf(vpc - vpd);
        float G = 4.0f * (log1p_half(spec) * log1p_half(temp));
        float R;
        asm("rcp.approx.f32 %0, %1;" : "=f"(R) : "f"(G + EPSF));
        Sq[r][cl]  = make_float4(spec, temp, R, (vpd + vpf) - vpc);
        Spf[r][cl] = (vpf >= EPSF) ? vpf : __int_as_float(0x7fffffff); // NaN
    }
    __syncthreads();

    const float thr = g_thr;

    // center thresholds: own-plane spec/temp from smem, other-plane from regs
    float ms[2], mt[2], lo[2], hi[2];
    #pragma unroll
    for (int o = 0; o < 2; ++o) {
        float4 qc = Sq[row0 + o + 7][tx + 7];
        ms[o] = fmaxf(qc.x, osp[o]) + SPEC_U;
        mt[o] = fmaxf(qc.y, otp[o]) + TEMP_U;
        float pfc = Spf[row0 + o + 7][tx + 7];   // may be NaN
        lo[o] = pfc - thr;
        hi[o] = pfc + thr;
    }

    float S0[2] = {0.f, 0.f};
    float S1[2] = {0.f, 0.f};

    #define ROW(RR, A, B) do_row<RR, A, B>(&Sq[row0 + RR][tx], &Spf[row0 + RR][tx], \
                                           ms, mt, lo, hi, S0, S1);
    ROW(0,  0, 0)
    ROW(1,  0, 1)  ROW(2,  0, 1)  ROW(3,  0, 1)  ROW(4,  0, 1)
    ROW(5,  0, 1)  ROW(6,  0, 1)  ROW(7,  0, 1)  ROW(8,  0, 1)
    ROW(9,  0, 1)  ROW(10, 0, 1)  ROW(11, 0, 1)  ROW(12, 0, 1)
    ROW(13, 0, 1)  ROW(14, 0, 1)
    ROW(15, 1, 1)
    #undef ROW

    const int ox = tx0 + tx;
    #pragma unroll
    for (int o = 0; o < 2; ++o) {
        int oy = ty0 + row0 + o;
        g_ps[pz][oy * OHW + ox] = make_float2(S0[o], S1[o]);
    }
}

// ---------------- pass 3: combine t-partials ----------------
__global__ __launch_bounds__(256)
void combine_kernel(float* __restrict__ out)
{
    int i = blockIdx.x * blockDim.x + threadIdx.x;    // 0 .. NBC*NOUT-1
    if (i >= NBC * NOUT) return;
    int bc  = i / NOUT;
    int pix = i - bc * NOUT;
    float2 a = g_ps[bc * 2 + 0][pix];
    float2 b = g_ps[bc * 2 + 1][pix];
    out[i] = (a.y + b.y) / ((a.x + b.x) + EPSF);
}

// ---------------- launch ----------------
extern "C" void kernel_launch(void* const* d_in, const int* in_sizes, int n_in,
                              void* d_out, int out_size)
{
    const float* pc = (const float*)d_in[0];   // prior_coarse (2,4,2,110,110)
    const float* pf = (const float*)d_in[1];   // prior_fine   (2,4,2,110,110)
    const float* pd = (const float*)d_in[2];   // pred_coarse  (2,4,110,110)
    float* out = (float*)d_out;                // (2,4,96,96)

    reduce_kernel<<<RED_BLOCKS, RED_THREADS>>>(pf);

    dim3 grid(OHW / TOX, OHW / TOY, NPLANE);   // (3, 6, 16) = 288 CTAs
    dim3 block(32, 8);
    starfm_kernel<<<grid, block>>>(pc, pf, pd);

    combine_kernel<<<(NBC * NOUT + 255) / 256, 256>>>(out);
}

// round 12
// speedup vs baseline: 1.6705x; 1.0414x over previous
#include <cuda_runtime.h>
#include <math.h>

// ---------------- problem constants ----------------
#define H_IMG 110
#define W_IMG 110
#define NPIX  (H_IMG * W_IMG)      // 12100
#define OHW   96
#define NOUT  (OHW * OHW)          // 9216
#define NBC   8                    // b*c = 2*4
#define NPLANE (NBC * 2)           // 16 (bc, t)
#define EPSF  1e-8f
#define SPEC_U 1.4142135623730951e-3f
#define TEMP_U 1.4142135623730951e-3f

#define NCTA   288                 // grid (3,6,16)
#define RCHUNK 673                 // ceil(NPLANE*NPIX / NCTA)

// ---------------- scratch (static: no allocation allowed) ----------------
__device__ float  g_thr;
__device__ float2 g_ps[NPLANE][NOUT];     // odd-t planes' partials (S0, S1)
__device__ float  g_part[NCTA][3];
__device__ unsigned int g_ticket = 0;
__device__ int    g_flag = 0;             // thr-ready (sticky; value-safe)
__device__ int    g_pairflag[NBC * 18];   // per (bc, ytile, xtile) pair

__device__ __forceinline__ int wcount(int i) {   // #windows covering index i
    int lo = i - 14; if (lo < 0) lo = 0;
    int hi = i;      if (hi > 95) hi = 95;
    return hi - lo + 1;
}

__device__ __forceinline__ float warp_redf(float v) {
    #pragma unroll
    for (int o = 16; o > 0; o >>= 1) v += __shfl_down_sync(0xffffffffu, v, o);
    return v;
}
__device__ __forceinline__ double warp_redd(double v) {
    #pragma unroll
    for (int o = 16; o > 0; o >>= 1) v += __shfl_down_sync(0xffffffffu, v, o);
    return v;
}

// log(fl(1+x))/2 via atanh form; rel err ~4e-7, matches reference arg rounding
__device__ __forceinline__ float log1p_half(float x) {
    float u   = 1.0f + x;
    float xp  = u - 1.0f;        // exact (u in [1,2])
    float up1 = u + 1.0f;
    float ri;
    asm("rcp.approx.f32 %0, %1;" : "=f"(ri) : "f"(up1));
    float z  = xp * ri;          // z in [0, 1/3]
    float z2 = z * z;
    float p  = fmaf(z2, 0.0909090909f, 0.1111111111f);
    p = fmaf(p, z2, 0.1428571429f);
    p = fmaf(p, z2, 0.2f);
    p = fmaf(p, z2, 0.3333333333f);
    p = fmaf(p, z2, 1.0f);
    return z * p;
}

// invspat = 7/(d^2+7); constexpr folds to an immediate after full unroll
__host__ __device__ constexpr float inv_v(int dy, int dx) {
    return 7.0f / (float)((dy - 7) * (dy - 7) + (dx - 7) * (dx - 7) + 7);
}

// ---------------- single fused kernel ----------------
#define TOX 32
#define TOY 16
#define SMW (TOX + 14)    // 46
#define SMH (TOY + 14)    // 30

template<int RR, int OMIN, int OMAX>
__device__ __forceinline__ void do_row(const float4* __restrict__ rq,
                                       const float*  __restrict__ rpf,
                                       const float* ms, const float* mt,
                                       const float* lo, const float* hi,
                                       float* S0, float* S1)
{
    #pragma unroll
    for (int dx = 0; dx < 15; ++dx) {
        float4 q = rq[dx];
        float pf = rpf[dx];
        #pragma unroll
        for (int o = OMIN; o <= OMAX; ++o) {
            float w = q.z * inv_v(RR - o, dx);      // immediate multiplier
            bool pass = (q.x < ms[o]) & (q.y < mt[o]) &
                        (pf > lo[o]) & (pf < hi[o]);     // NaN -> false
            if (pass) {
                S0[o] += w;
                S1[o] = fmaf(w, q.w, S1[o]);
            }
        }
    }
}

__global__ __launch_bounds__(256, 2)
void starfm_kernel(const float* __restrict__ pcg,
                   const float* __restrict__ pfg,
                   const float* __restrict__ pdg,
                   float* __restrict__ out)
{
    __shared__ float4 Sq[SMH][SMW];
    __shared__ float  Spf[SMH][SMW];
    __shared__ float  smf[8][3];
    __shared__ double smd[8][3];
    __shared__ int    isLast;
    __shared__ float  sh_thr;

    const int pz  = blockIdx.z;           // plane = bc*2 + t
    const int bc  = pz >> 1;
    const int ty0 = blockIdx.y * TOY;
    const int tx0 = blockIdx.x * TOX;
    const int tx  = threadIdx.x, ty = threadIdx.y;   // block (32, 8)
    const int tid = ty * 32 + tx;
    const int row0 = 2 * ty;
    const int cta  = (blockIdx.z * 6 + blockIdx.y) * 3 + blockIdx.x;  // 0..287
    const int pairslot = (bc * 6 + blockIdx.y) * 3 + blockIdx.x;      // 0..143

    const int warp = tid >> 5, lane = tid & 31;

    // ================= phase 0: thr reduction slice =================
    {
        float c = 0.f, s = 0.f, s2 = 0.f;
        const int base = cta * RCHUNK;
        #pragma unroll
        for (int j = 0; j < 3; ++j) {
            int i = base + j * 256 + tid;
            if (i < base + RCHUNK && i < NPLANE * NPIX) {
                float vpf = pfg[i];
                if (vpf >= EPSF) {
                    int pix = i % NPIX;
                    int h = pix / W_IMG, w = pix - h * W_IMG;
                    float mult = (float)(wcount(h) * wcount(w));
                    c  += mult;
                    s  += mult * vpf;
                    s2 += mult * vpf * vpf;
                }
            }
        }
        c = warp_redf(c); s = warp_redf(s); s2 = warp_redf(s2);
        if (lane == 0) { smf[warp][0] = c; smf[warp][1] = s; smf[warp][2] = s2; }
        __syncthreads();
        if (tid == 0) {
            float C = 0, S = 0, S2 = 0;
            #pragma unroll
            for (int w = 0; w < 8; w++) { C += smf[w][0]; S += smf[w][1]; S2 += smf[w][2]; }
            g_part[cta][0] = C; g_part[cta][1] = S; g_part[cta][2] = S2;
            __threadfence();
            unsigned t = atomicAdd(&g_ticket, 1u);
            isLast = (t == NCTA - 1);
        }
        __syncthreads();
        if (isLast) {
            __threadfence();
            double cc = 0, ss = 0, ss2 = 0;
            for (int i = tid; i < NCTA; i += 256) {   // fixed order
                cc  += (double)g_part[i][0];
                ss  += (double)g_part[i][1];
                ss2 += (double)g_part[i][2];
            }
            cc = warp_redd(cc); ss = warp_redd(ss); ss2 = warp_redd(ss2);
            if (lane == 0) { smd[warp][0] = cc; smd[warp][1] = ss; smd[warp][2] = ss2; }
            __syncthreads();
            if (tid == 0) {
                double C = 0, S = 0, S2 = 0;
                #pragma unroll
                for (int w = 0; w < 8; w++) { C += smd[w][0]; S += smd[w][1]; S2 += smd[w][2]; }
                double m = S / C, m2 = S2 / C;
                g_thr = (float)(2.0 * sqrt(m2 - m * m) / 5.0);
                g_ticket = 0;                  // every call recomputes
                __threadfence();
                atomicExch(&g_flag, 1);
            }
        }
    }

    // ================= phase 1: stage + inline precompute =================
    const float* pcp = pcg + (size_t)pz * NPIX;
    const float* pfp = pfg + (size_t)pz * NPIX;
    const float* pdp = pdg + (size_t)bc * NPIX;

    // other-plane center spec/temp (LDGs overlap staging)
    const int oz = pz ^ 1;
    float osp[2], otp[2];
    #pragma unroll
    for (int o = 0; o < 2; ++o) {
        int cg = (ty0 + row0 + o + 7) * W_IMG + (tx0 + tx + 7);
        float c2 = pcg[(size_t)oz * NPIX + cg];
        float f2 = pfg[(size_t)oz * NPIX + cg];
        float d2 = pdp[cg];
        osp[o] = fabsf(c2 - f2);
        otp[o] = fabsf(c2 - d2);
    }

    for (int i = tid; i < SMH * SMW; i += 256) {
        int r  = i / SMW;
        int cl = i - r * SMW;
        int g  = (ty0 + r) * W_IMG + (tx0 + cl);
        float vpc = pcp[g];
        float vpf = pfp[g];
        float vpd = pdp[g];
        float spec = fabsf(vpc - vpf);
        float temp = fabsf(vpc - vpd);
        float G = 4.0f * (log1p_half(spec) * log1p_half(temp));
        float R;
        asm("rcp.approx.f32 %0, %1;" : "=f"(R) : "f"(G + EPSF));
        Sq[r][cl]  = make_float4(spec, temp, R, (vpd + vpf) - vpc);
        Spf[r][cl] = (vpf >= EPSF) ? vpf : __int_as_float(0x7fffffff); // NaN
    }

    // wait for thr (reducer finished long ago in the common case)
    if (tid == 0) {
        while (*(volatile int*)&g_flag == 0) { }
        __threadfence();
        sh_thr = *(volatile float*)&g_thr;
    }
    __syncthreads();
    const float thr = sh_thr;

    // center thresholds
    float ms[2], mt[2], lo[2], hi[2];
    #pragma unroll
    for (int o = 0; o < 2; ++o) {
        float4 qc = Sq[row0 + o + 7][tx + 7];
        ms[o] = fmaxf(qc.x, osp[o]) + SPEC_U;
        mt[o] = fmaxf(qc.y, otp[o]) + TEMP_U;
        float pfc = Spf[row0 + o + 7][tx + 7];   // may be NaN
        lo[o] = pfc - thr;
        hi[o] = pfc + thr;
    }

    // ================= phase 2: window loop =================
    float S0[2] = {0.f, 0.f};
    float S1[2] = {0.f, 0.f};

    #define ROW(RR, A, B) do_row<RR, A, B>(&Sq[row0 + RR][tx], &Spf[row0 + RR][tx], \
                                           ms, mt, lo, hi, S0, S1);
    ROW(0,  0, 0)
    ROW(1,  0, 1)  ROW(2,  0, 1)  ROW(3,  0, 1)  ROW(4,  0, 1)
    ROW(5,  0, 1)  ROW(6,  0, 1)  ROW(7,  0, 1)  ROW(8,  0, 1)
    ROW(9,  0, 1)  ROW(10, 0, 1)  ROW(11, 0, 1)  ROW(12, 0, 1)
    ROW(13, 0, 1)  ROW(14, 0, 1)
    ROW(15, 1, 1)
    #undef ROW

    // ================= phase 3: pair combine + output =================
    const int ox = tx0 + tx;
    if (pz & 1) {
        // t=1: publish partials to the pair's t=0 CTA
        #pragma unroll
        for (int o = 0; o < 2; ++o) {
            int oy = ty0 + row0 + o;
            g_ps[pz][oy * OHW + ox] = make_float2(S0[o], S1[o]);
        }
        __threadfence();
        __syncthreads();
        if (tid == 0) atomicExch(&g_pairflag[pairslot], 1);
    } else {
        // t=0: wait for partner, combine (same add order as old combine), write
        if (tid == 0) {
            while (*(volatile int*)&g_pairflag[pairslot] == 0) { }
            __threadfence();
        }
        __syncthreads();
        #pragma unroll
        for (int o = 0; o < 2; ++o) {
            int oy = ty0 + row0 + o;
            float2 p = g_ps[pz ^ 1][oy * OHW + ox];
            float s0 = S0[o] + p.x;
            float s1 = S1[o] + p.y;
            out[(size_t)bc * NOUT + oy * OHW + ox] = s1 / (s0 + EPSF);
        }
    }
}

// ---------------- launch ----------------
extern "C" void kernel_launch(void* const* d_in, const int* in_sizes, int n_in,
                              void* d_out, int out_size)
{
    const float* pc = (const float*)d_in[0];   // prior_coarse (2,4,2,110,110)
    const float* pf = (const float*)d_in[1];   // prior_fine   (2,4,2,110,110)
    const float* pd = (const float*)d_in[2];   // pred_coarse  (2,4,110,110)
    float* out = (float*)d_out;                // (2,4,96,96)

    dim3 grid(OHW / TOX, OHW / TOY, NPLANE);   // (3, 6, 16) = 288 CTAs, one wave
    dim3 block(32, 8);
    starfm_kernel<<<grid, block>>>(pc, pf, pd, out);
}